// round 9
// baseline (speedup 1.0000x reference)
#include <cuda_runtime.h>
#include <cuda_fp16.h>
#include <math.h>

#define NPAIR 32      // 64 real batches packed as 32 complex images
#define HIN   512
#define WIN   512
#define NP    768     // padded size (both dims)
#define PAD   128
#define NZROWS 512    // nonzero padded rows: y in [PAD, PAD+512)

// padded smem element index: +1 float2 per 16 to break power-of-2 stride conflicts
#define P_(i) ((i) + ((i) >> 4))

#define BUFR  3264    // row kernels: 4 lines, >= P_(3071)+1
#define LLEN  816     // per-line stride in row kernels: >= P_(767)+1
#define EBUF  816
#define BUFC  6528    // col kernel: 8 interleaved lines, >= P_(6143)+1
#define SMEM_COL_BYTES ((BUFC + EBUF) * sizeof(float2))   // 58752

__device__ __half2 g_buf[NPAIR * NP * NP];  // 75 MB fp16 complex scratch
__device__ float2  g_E[NP];                 // e^{-2*pi*i*m/768}

static __device__ __forceinline__ float2 cmul(float2 a, float2 b) {
    return make_float2(a.x*b.x - a.y*b.y, a.x*b.y + a.y*b.x);
}
static __device__ __forceinline__ float2 cadd(float2 a, float2 b) { return make_float2(a.x+b.x, a.y+b.y); }
static __device__ __forceinline__ float2 csub(float2 a, float2 b) { return make_float2(a.x-b.x, a.y-b.y); }
static __device__ __forceinline__ float2 cconj(float2 a) { return make_float2(a.x, -a.y); }
static __device__ __forceinline__ float2 mul_mi(float2 a) { return make_float2(a.y, -a.x); }  // *(-i)
static __device__ __forceinline__ float2 mul_pi(float2 a) { return make_float2(-a.y, a.x); }  // *(+i)

static __device__ __forceinline__ float2 ldh(const __half2* p) { return __half22float2(*p); }
static __device__ __forceinline__ void sth(__half2* p, float2 v) { *p = __floats2half2_rn(v.x, v.y); }

__global__ void k_init_E() {
    int t = threadIdx.x;
    if (t < NP) {
        double a = -2.0 * 3.14159265358979323846 * (double)t / (double)NP;
        g_E[t] = make_float2((float)cos(a), (float)sin(a));
    }
}

// sync functors: block-wide vs per-line (96-thread named barrier)
struct SyncBlock { __device__ __forceinline__ void operator()() const { __syncthreads(); } };
struct SyncLine  {
    int id;
    __device__ __forceinline__ void operator()() const {
        asm volatile("bar.sync %0, 96;" :: "r"(id) : "memory");
    }
};

// ---------------- register DFT kernels ----------------
template<bool INV>
static __device__ __forceinline__ void dft4(float2 v[4]) {
    float2 t0 = cadd(v[0], v[2]), t1 = csub(v[0], v[2]);
    float2 t2 = cadd(v[1], v[3]), t3 = csub(v[1], v[3]);
    float2 jt3 = INV ? mul_pi(t3) : mul_mi(t3);
    v[0] = cadd(t0, t2); v[2] = csub(t0, t2);
    v[1] = cadd(t1, jt3); v[3] = csub(t1, jt3);
}

template<bool INV>
static __device__ __forceinline__ void dft8(float2 v[8]) {
    float2 e[4] = {v[0], v[2], v[4], v[6]};
    float2 o[4] = {v[1], v[3], v[5], v[7]};
    dft4<INV>(e); dft4<INV>(o);
    const float rh = 0.70710678118654752f;
    o[1] = cmul(o[1], make_float2(rh, INV ? rh : -rh));
    o[2] = INV ? mul_pi(o[2]) : mul_mi(o[2]);
    o[3] = cmul(o[3], make_float2(-rh, INV ? rh : -rh));
#pragma unroll
    for (int k = 0; k < 4; k++) { v[k] = cadd(e[k], o[k]); v[k+4] = csub(e[k], o[k]); }
}

// 12-point DFT, natural-order in and out.  12 = 4 x 3 Cooley-Tukey.
template<bool INV>
static __device__ __forceinline__ void dft12(float2 v[12]) {
    const float H = 0.5f, S = 0.8660254037844386f;
    float2 c0[4], c1[4], c2[4];
    {
        float2 b[4];
        b[0]=v[0]; b[1]=v[3]; b[2]=v[6]; b[3]=v[9];  dft4<INV>(b);
        c0[0]=b[0]; c0[1]=b[1]; c0[2]=b[2]; c0[3]=b[3];
        b[0]=v[1]; b[1]=v[4]; b[2]=v[7]; b[3]=v[10]; dft4<INV>(b);
        c1[0]=b[0]; c1[1]=b[1]; c1[2]=b[2]; c1[3]=b[3];
        b[0]=v[2]; b[1]=v[5]; b[2]=v[8]; b[3]=v[11]; dft4<INV>(b);
        c2[0]=b[0]; c2[1]=b[1]; c2[2]=b[2]; c2[3]=b[3];
    }
    const float sgn = INV ? 1.f : -1.f;
    c1[1] = cmul(c1[1], make_float2(S, sgn*H));
    c1[2] = cmul(c1[2], make_float2(H, sgn*S));
    c1[3] = INV ? mul_pi(c1[3]) : mul_mi(c1[3]);
    c2[1] = cmul(c2[1], make_float2(H,  sgn*S));
    c2[2] = cmul(c2[2], make_float2(-H, sgn*S));
    c2[3] = make_float2(-c2[3].x, -c2[3].y);
    const float d = INV ? S : -S;
#pragma unroll
    for (int k1 = 0; k1 < 4; k1++) {
        float2 t = cadd(c1[k1], c2[k1]);
        float2 u = csub(c1[k1], c2[k1]);
        float2 x0 = cadd(c0[k1], t);
        float2 m = make_float2(c0[k1].x - 0.5f*t.x, c0[k1].y - 0.5f*t.y);
        float2 idu = make_float2(-d*u.y, d*u.x);
        v[k1]     = x0;
        v[4 + k1] = cadd(m, idu);
        v[8 + k1] = csub(m, idu);
    }
}

// ---------------- Stockham stages: 768 = 8(NS=1) * 12(NS=8) * 8(NS=96) ----------------
// Twiddle indices never exceed 767 in this factorization -> direct E lookups, no chain.
struct MapRow {
    int base;
    __device__ __forceinline__ int operator()(int e) const { return base + P_(e); }
};
struct MapCol8 {
    int tx;
    __device__ __forceinline__ int operator()(int e) const { int b = (e << 3) + tx; return P_(b); }
};

template<bool INV, class M>
static __device__ __forceinline__ void stage1_store(float2 v[8], float2* buf, int j, M map) {
    dft8<INV>(v);
#pragma unroll
    for (int s = 0; s < 8; s++) buf[map(8*j + s)] = v[s];
}

// active = (j < 64). ALL threads of the sync group must call (contains barriers).
template<bool INV, class M, class SY>
static __device__ __forceinline__ void stage2_r12(float2* buf, const float2* E, int j, bool active, M map, SY sync) {
    float2 v[12];
    int m = j & 7;
    if (active) {
#pragma unroll
        for (int r = 0; r < 12; r++) v[r] = buf[map(j + 64*r)];
#pragma unroll
        for (int r = 1; r < 12; r++) {
            float2 w = E[P_(8*m*r)];             // 8*7*11 = 616 < 768
            if (INV) w.y = -w.y;
            v[r] = cmul(v[r], w);
        }
        dft12<INV>(v);
    }
    sync();
    if (active) {
        int base = 12*j - 11*m;
#pragma unroll
        for (int s = 0; s < 12; s++) buf[map(base + 8*s)] = v[s];
    }
    sync();
}

// output in v: v[s] = X[j + 96 s]
template<bool INV, class M>
static __device__ __forceinline__ void stage3_r8(const float2* buf, const float2* E, int j, M map, float2 v[8]) {
#pragma unroll
    for (int r = 0; r < 8; r++) v[r] = buf[map(j + 96*r)];
#pragma unroll
    for (int r = 1; r < 8; r++) {
        float2 w = E[P_(j*r)];                   // 95*7 = 665 < 768
        if (INV) w.y = -w.y;
        v[r] = cmul(v[r], w);
    }
    dft8<INV>(v);
}

// ---------------- Pass 1: pad + pack pairs + forward row FFT (512 rows/image) ----------------
__global__ __launch_bounds__(384) void k_row_fwd(const float* __restrict__ x)
{
    __shared__ float2 SB[BUFR];
    __shared__ float2 SE[EBUF];
    int t = threadIdx.x;
    for (int i = t; i < NP; i += 384) SE[P_(i)] = g_E[i];
    int sub = t / 96, jj = t - sub * 96;
    int p = blockIdx.x >> 7;                    // /128
    int r = ((blockIdx.x & 127) << 2) + sub;    // row in [0,512)
    int y = PAD + r;
    const float* r1 = x + ((size_t)(2*p)     * HIN + r) * WIN;
    const float* r2 = x + ((size_t)(2*p + 1) * HIN + r) * WIN;
    float2 v[8];
#pragma unroll
    for (int rr = 0; rr < 8; rr++) {
        int xi = jj + 96*rr;
        float2 val = make_float2(0.f, 0.f);
        if (xi >= PAD && xi < PAD + WIN) {
            val.x = r1[xi - PAD];
            val.y = r2[xi - PAD];
        }
        v[rr] = val;
    }
    MapRow map; map.base = sub * LLEN;
    stage1_store<false>(v, SB, jj, map);
    __syncthreads();                            // SE + stage1 visible (block-wide once)
    SyncLine ln; ln.id = sub + 1;
    stage2_r12<false>(SB, SE, jj, jj < 64, map, ln);
    float2 u[8];
    stage3_r8<false>(SB, SE, jj, map, u);
    __half2* o = g_buf + ((size_t)p * NP + y) * NP;
#pragma unroll
    for (int s = 0; s < 8; s++) sth(o + jj + 96*s, u[s]);
}

// ---------------- Pass 2: column FFT * G * column IFFT (8 columns/block, in place) ----------------
__global__ __launch_bounds__(768) void k_col(const float* __restrict__ w)
{
    extern __shared__ float2 smc[];
    float2* SB = smc;            // interleaved 8 lines, padded
    float2* SE = smc + BUFC;
    int t = threadIdx.x;
    for (int i = t; i < NP; i += 768) SE[P_(i)] = g_E[i];
    int tx = t & 7;
    int jj = t >> 3;                            // [0,96)
    int p = blockIdx.x / 96;
    int g = blockIdx.x - p * 96;
    int kx = (g << 3) + tx;
    __half2* base = g_buf + (size_t)p * NP * NP;
    MapCol8 map; map.tx = tx;

    float2 v[8];
#pragma unroll
    for (int rr = 0; rr < 8; rr++) {
        int y = jj + 96*rr;
        float2 val = make_float2(0.f, 0.f);
        if (y >= PAD && y < PAD + NZROWS)
            val = ldh(base + (size_t)y * NP + kx);
        v[rr] = val;
    }
    stage1_store<false>(v, SB, jj, map);
    __syncthreads();
    SyncBlock bs;
    stage2_r12<false>(SB, SE, jj, jj < 64, map, bs);
    float2 u[8];
    stage3_r8<false>(SB, SE, jj, map, u);       // u[s] = spectrum at ky = jj+96s

    // filter coefficients for this kx (replicates reference exactly)
    int jp = (kx <= 384) ? kx : (NP - kx);
    int j2 = (jp == 0) ? 0 : ((jp == 384) ? 1 : (385 - jp));
    float2 D1[3], D2[3];
#pragma unroll
    for (int a = 0; a < 3; a++) {
        float2 s1 = make_float2(0.f, 0.f), s2 = make_float2(0.f, 0.f);
#pragma unroll
        for (int b = 0; b < 3; b++) {
            float wv = w[a * 3 + b];
            int i1 = (jp * b) % NP;
            int i2 = (j2 * b) % NP;
            float2 e1 = SE[P_(i1)], e2 = SE[P_(i2)];
            s1.x += wv * e1.x; s1.y += wv * e1.y;
            s2.x += wv * e2.x; s2.y += wv * e2.y;
        }
        D1[a] = s1; D2[a] = s2;
    }
    const float scale = 1.0f / ((float)NP * (float)NP);
#pragma unroll
    for (int s = 0; s < 8; s++) {
        int ky = jj + 96*s;
        float2 e1 = SE[P_(ky)];
        int k2i = 2 * ky; if (k2i >= NP) k2i -= NP;
        float2 e2 = SE[P_(k2i)];
        float2 c1 = cconj(e1), c2 = cconj(e2);
        float2 hp1 = cadd(D1[0], cadd(cmul(e1, D1[1]), cmul(e2, D1[2])));
        float2 hm1 = cadd(D1[0], cadd(cmul(c1, D1[1]), cmul(c2, D1[2])));
        float2 hp2 = cadd(D2[0], cadd(cmul(e1, D2[1]), cmul(e2, D2[2])));
        float2 hm2 = cadd(D2[0], cadd(cmul(c1, D2[1]), cmul(c2, D2[2])));
        float2 P = cmul(cmul(hp1, hm1), cmul(hp2, hm2));
        float inv = 1.0f / (P.x * P.x + P.y * P.y);
        float2 G = make_float2(P.x * inv, -P.y * inv);
        if (kx == 384)      G.y = 0.0f;    // irfft drops imag at Nyquist column
        else if (kx > 384)  G.y = -G.y;    // Hermitian mirror half
        G.x *= scale; G.y *= scale;
        u[s] = cmul(u[s], G);
    }

    // inverse FFT: u[r] is exactly X[jj + 96r] = stage-1 input -> fuse in registers
    dft8<true>(u);
    __syncthreads();                            // all forward stage-3 reads of SB done
#pragma unroll
    for (int s = 0; s < 8; s++) SB[map(8*jj + s)] = u[s];
    __syncthreads();
    stage2_r12<true>(SB, SE, jj, jj < 64, map, bs);
    float2 z[8];
    stage3_r8<true>(SB, SE, jj, map, z);
#pragma unroll
    for (int s = 0; s < 8; s++) {
        int y = jj + 96*s;
        sth(base + (size_t)y * NP + kx, z[s]);
    }
}

// ---------------- Pass 3: inverse row FFT + unpack pairs ----------------
__global__ __launch_bounds__(384) void k_row_inv(float* __restrict__ out)
{
    __shared__ float2 SB[BUFR];
    __shared__ float2 SE[EBUF];
    int t = threadIdx.x;
    for (int i = t; i < NP; i += 384) SE[P_(i)] = g_E[i];
    int sub = t / 96, jj = t - sub * 96;
    int p = blockIdx.x / 192;
    int y = ((blockIdx.x - p * 192) << 2) + sub;
    const __half2* in = g_buf + ((size_t)p * NP + y) * NP;
    float2 v[8];
#pragma unroll
    for (int rr = 0; rr < 8; rr++) v[rr] = ldh(in + jj + 96*rr);
    MapRow map; map.base = sub * LLEN;
    stage1_store<true>(v, SB, jj, map);
    __syncthreads();
    SyncLine ln; ln.id = sub + 1;
    stage2_r12<true>(SB, SE, jj, jj < 64, map, ln);
    float2 u[8];
    stage3_r8<true>(SB, SE, jj, map, u);
    float* o1 = out + ((size_t)(2*p)     * NP + y) * NP;
    float* o2 = out + ((size_t)(2*p + 1) * NP + y) * NP;
#pragma unroll
    for (int s = 0; s < 8; s++) {
        int xi = jj + 96*s;
        o1[xi] = u[s].x;
        o2[xi] = u[s].y;
    }
}

extern "C" void kernel_launch(void* const* d_in, const int* in_sizes, int n_in,
                              void* d_out, int out_size)
{
    const float* x = (const float*)d_in[0];
    const float* w = (const float*)d_in[1];
    if (n_in >= 2 && in_sizes[0] == 9) {  // safety: metadata order w,x
        const float* tmp = x; x = w; w = tmp;
    }
    float* out = (float*)d_out;

    cudaFuncSetAttribute(k_col, cudaFuncAttributeMaxDynamicSharedMemorySize, (int)SMEM_COL_BYTES);

    k_init_E<<<1, NP>>>();
    k_row_fwd<<<NPAIR * NZROWS / 4, 384>>>(x);
    k_col    <<<NPAIR * 96, 768, SMEM_COL_BYTES>>>(w);
    k_row_inv<<<NPAIR * NP / 4, 384>>>(out);
}

// round 11
// speedup vs baseline: 1.6566x; 1.6566x over previous
#include <cuda_runtime.h>
#include <cuda_fp16.h>
#include <math.h>

#define NPAIR 32      // 64 real batches packed as 32 complex images
#define HIN   512
#define WIN   512
#define NP    768     // padded size (both dims)
#define PAD   128
#define NZROWS 512    // nonzero padded rows: y in [PAD, PAD+512)

// padded smem element index: +1 float2 per 16 to break power-of-2 stride conflicts
#define P_(i) ((i) + ((i) >> 4))

#define BUF   3264    // block-wide float2 data buffer: >= P_(3071)+1
#define LLEN  816     // per-line stride in row kernels: >= P_(767)+1
#define EBUF  816

__device__ __half2 g_buf[NPAIR * NP * NP];  // 75 MB fp16 complex scratch
__device__ float2  g_E[NP];                 // e^{-2*pi*i*m/768}

static __device__ __forceinline__ float2 cmul(float2 a, float2 b) {
    return make_float2(a.x*b.x - a.y*b.y, a.x*b.y + a.y*b.x);
}
static __device__ __forceinline__ float2 cadd(float2 a, float2 b) { return make_float2(a.x+b.x, a.y+b.y); }
static __device__ __forceinline__ float2 csub(float2 a, float2 b) { return make_float2(a.x-b.x, a.y-b.y); }
static __device__ __forceinline__ float2 cconj(float2 a) { return make_float2(a.x, -a.y); }
static __device__ __forceinline__ float2 mul_mi(float2 a) { return make_float2(a.y, -a.x); }  // *(-i)
static __device__ __forceinline__ float2 mul_pi(float2 a) { return make_float2(-a.y, a.x); }  // *(+i)

static __device__ __forceinline__ float2 ldh(const __half2* p) { return __half22float2(*p); }
static __device__ __forceinline__ void sth(__half2* p, float2 v) { *p = __floats2half2_rn(v.x, v.y); }

__global__ void k_init_E() {
    int t = threadIdx.x;
    if (t < NP) {
        double a = -2.0 * 3.14159265358979323846 * (double)t / (double)NP;
        g_E[t] = make_float2((float)cos(a), (float)sin(a));
    }
}

// ---------------- register DFT kernels ----------------
template<bool INV>
static __device__ __forceinline__ void dft4(float2 v[4]) {
    float2 t0 = cadd(v[0], v[2]), t1 = csub(v[0], v[2]);
    float2 t2 = cadd(v[1], v[3]), t3 = csub(v[1], v[3]);
    float2 jt3 = INV ? mul_pi(t3) : mul_mi(t3);
    v[0] = cadd(t0, t2); v[2] = csub(t0, t2);
    v[1] = cadd(t1, jt3); v[3] = csub(t1, jt3);
}

template<bool INV>
static __device__ __forceinline__ void dft8(float2 v[8]) {
    float2 e[4] = {v[0], v[2], v[4], v[6]};
    float2 o[4] = {v[1], v[3], v[5], v[7]};
    dft4<INV>(e); dft4<INV>(o);
    const float rh = 0.70710678118654752f;
    o[1] = cmul(o[1], make_float2(rh, INV ? rh : -rh));
    o[2] = INV ? mul_pi(o[2]) : mul_mi(o[2]);
    o[3] = cmul(o[3], make_float2(-rh, INV ? rh : -rh));
#pragma unroll
    for (int k = 0; k < 4; k++) { v[k] = cadd(e[k], o[k]); v[k+4] = csub(e[k], o[k]); }
}

// 12-point DFT, natural-order in and out.  12 = 4 x 3 Cooley-Tukey.
template<bool INV>
static __device__ __forceinline__ void dft12(float2 v[12]) {
    const float H = 0.5f, S = 0.8660254037844386f;
    float2 c0[4], c1[4], c2[4];
    {
        float2 b[4];
        b[0]=v[0]; b[1]=v[3]; b[2]=v[6]; b[3]=v[9];  dft4<INV>(b);
        c0[0]=b[0]; c0[1]=b[1]; c0[2]=b[2]; c0[3]=b[3];
        b[0]=v[1]; b[1]=v[4]; b[2]=v[7]; b[3]=v[10]; dft4<INV>(b);
        c1[0]=b[0]; c1[1]=b[1]; c1[2]=b[2]; c1[3]=b[3];
        b[0]=v[2]; b[1]=v[5]; b[2]=v[8]; b[3]=v[11]; dft4<INV>(b);
        c2[0]=b[0]; c2[1]=b[1]; c2[2]=b[2]; c2[3]=b[3];
    }
    const float sgn = INV ? 1.f : -1.f;
    c1[1] = cmul(c1[1], make_float2(S, sgn*H));
    c1[2] = cmul(c1[2], make_float2(H, sgn*S));
    c1[3] = INV ? mul_pi(c1[3]) : mul_mi(c1[3]);
    c2[1] = cmul(c2[1], make_float2(H,  sgn*S));
    c2[2] = cmul(c2[2], make_float2(-H, sgn*S));
    c2[3] = make_float2(-c2[3].x, -c2[3].y);
    const float d = INV ? S : -S;
#pragma unroll
    for (int k1 = 0; k1 < 4; k1++) {
        float2 t = cadd(c1[k1], c2[k1]);
        float2 u = csub(c1[k1], c2[k1]);
        float2 x0 = cadd(c0[k1], t);
        float2 m = make_float2(c0[k1].x - 0.5f*t.x, c0[k1].y - 0.5f*t.y);
        float2 idu = make_float2(-d*u.y, d*u.x);
        v[k1]     = x0;
        v[4 + k1] = cadd(m, idu);
        v[8 + k1] = csub(m, idu);
    }
}

// log-depth twiddle powers: tw[r] = w1^r, depth <= ceil(log2 r); pure registers.
template<int N>
static __device__ __forceinline__ void twpow(float2 w1, float2 tw[N]) {
    tw[1] = w1;
#pragma unroll
    for (int r = 2; r < N; r++) tw[r] = cmul(tw[r >> 1], tw[r - (r >> 1)]);
}

// ---------------- Stockham stages: 768 = 8(NS=1) * 12(NS=8) * 8(NS=96) ----------------
struct MapRow {
    int base;
    __device__ __forceinline__ int operator()(int e) const { return base + P_(e); }
};
struct MapCol {
    int tx;
    __device__ __forceinline__ int operator()(int e) const { int b = (e << 2) + tx; return P_(b); }
};

template<bool INV, class M>
static __device__ __forceinline__ void stage1_store(float2 v[8], float2* buf, int j, M map) {
    dft8<INV>(v);
#pragma unroll
    for (int s = 0; s < 8; s++) buf[map(8*j + s)] = v[s];
}

// active = (j < 64). ALL threads must call (contains block barrier).
template<bool INV, class M>
static __device__ __forceinline__ void stage2_r12(float2* buf, const float2* E, int j, bool active, M map) {
    float2 v[12];
    int m = j & 7;
    if (active) {
#pragma unroll
        for (int r = 0; r < 12; r++) v[r] = buf[map(j + 64*r)];
        float2 w1 = E[P_(8*m)];
        if (INV) w1.y = -w1.y;
        float2 tw[12];
        twpow<12>(w1, tw);
#pragma unroll
        for (int r = 1; r < 12; r++) v[r] = cmul(v[r], tw[r]);
        dft12<INV>(v);
    }
    __syncthreads();
    if (active) {
        int base = 12*j - 11*m;
#pragma unroll
        for (int s = 0; s < 12; s++) buf[map(base + 8*s)] = v[s];
    }
    __syncthreads();
}

// output in v: v[s] = X[j + 96 s]
template<bool INV, class M>
static __device__ __forceinline__ void stage3_r8(const float2* buf, const float2* E, int j, M map, float2 v[8]) {
#pragma unroll
    for (int r = 0; r < 8; r++) v[r] = buf[map(j + 96*r)];
    float2 w1 = E[P_(j)];
    if (INV) w1.y = -w1.y;
    float2 tw[8];
    twpow<8>(w1, tw);
#pragma unroll
    for (int r = 1; r < 8; r++) v[r] = cmul(v[r], tw[r]);
    dft8<INV>(v);
}

// ---------------- Pass 1: pad + pack pairs + forward row FFT (512 rows/image) ----------------
__global__ __launch_bounds__(384) void k_row_fwd(const float* __restrict__ x)
{
    __shared__ float2 SB[BUF];
    __shared__ float2 SE[EBUF];
    int t = threadIdx.x;
    for (int i = t; i < NP; i += 384) SE[P_(i)] = g_E[i];
    int sub = t / 96, jj = t - sub * 96;
    int p = blockIdx.x >> 7;                    // /128
    int r = ((blockIdx.x & 127) << 2) + sub;    // row in [0,512)
    int y = PAD + r;
    const float* r1 = x + ((size_t)(2*p)     * HIN + r) * WIN;
    const float* r2 = x + ((size_t)(2*p + 1) * HIN + r) * WIN;
    float2 v[8];
#pragma unroll
    for (int rr = 0; rr < 8; rr++) {
        int xi = jj + 96*rr;
        float2 val = make_float2(0.f, 0.f);
        if (xi >= PAD && xi < PAD + WIN) {
            val.x = r1[xi - PAD];
            val.y = r2[xi - PAD];
        }
        v[rr] = val;
    }
    MapRow map; map.base = sub * LLEN;
    stage1_store<false>(v, SB, jj, map);
    __syncthreads();                            // SE + stage1 visible
    stage2_r12<false>(SB, SE, jj, jj < 64, map);
    float2 u[8];
    stage3_r8<false>(SB, SE, jj, map, u);
    __half2* o = g_buf + ((size_t)p * NP + y) * NP;
#pragma unroll
    for (int s = 0; s < 8; s++) sth(o + jj + 96*s, u[s]);
}

// ---------------- Pass 2: column FFT * G * column IFFT (in place) ----------------
__global__ __launch_bounds__(384) void k_col(const float* __restrict__ w)
{
    __shared__ float2 SB[BUF];
    __shared__ float2 SE[EBUF];
    int t = threadIdx.x;
    for (int i = t; i < NP; i += 384) SE[P_(i)] = g_E[i];
    int tx = t & 3;
    int jj = t >> 2;                            // [0,96)
    int p = blockIdx.x / 192;
    int g = blockIdx.x - p * 192;
    int kx = (g << 2) + tx;
    __half2* base = g_buf + (size_t)p * NP * NP;
    MapCol map; map.tx = tx;

    float2 v[8];
#pragma unroll
    for (int rr = 0; rr < 8; rr++) {
        int y = jj + 96*rr;
        float2 val = make_float2(0.f, 0.f);
        if (y >= PAD && y < PAD + NZROWS)
            val = ldh(base + (size_t)y * NP + kx);
        v[rr] = val;
    }
    stage1_store<false>(v, SB, jj, map);
    __syncthreads();
    stage2_r12<false>(SB, SE, jj, jj < 64, map);
    float2 u[8];
    stage3_r8<false>(SB, SE, jj, map, u);       // u[s] = spectrum at ky = jj+96s

    // filter coefficients for this kx (replicates reference exactly)
    int jp = (kx <= 384) ? kx : (NP - kx);
    int j2 = (jp == 0) ? 0 : ((jp == 384) ? 1 : (385 - jp));
    float2 D1[3], D2[3];
#pragma unroll
    for (int a = 0; a < 3; a++) {
        float2 s1 = make_float2(0.f, 0.f), s2 = make_float2(0.f, 0.f);
#pragma unroll
        for (int b = 0; b < 3; b++) {
            float wv = w[a * 3 + b];
            int i1 = (jp * b) % NP;
            int i2 = (j2 * b) % NP;
            float2 e1 = SE[P_(i1)], e2 = SE[P_(i2)];
            s1.x += wv * e1.x; s1.y += wv * e1.y;
            s2.x += wv * e2.x; s2.y += wv * e2.y;
        }
        D1[a] = s1; D2[a] = s2;
    }
    const float scale = 1.0f / ((float)NP * (float)NP);
#pragma unroll
    for (int s = 0; s < 8; s++) {
        int ky = jj + 96*s;
        float2 e1 = SE[P_(ky)];
        int k2i = 2 * ky; if (k2i >= NP) k2i -= NP;
        float2 e2 = SE[P_(k2i)];
        float2 c1 = cconj(e1), c2 = cconj(e2);
        float2 hp1 = cadd(D1[0], cadd(cmul(e1, D1[1]), cmul(e2, D1[2])));
        float2 hm1 = cadd(D1[0], cadd(cmul(c1, D1[1]), cmul(c2, D1[2])));
        float2 hp2 = cadd(D2[0], cadd(cmul(e1, D2[1]), cmul(e2, D2[2])));
        float2 hm2 = cadd(D2[0], cadd(cmul(c1, D2[1]), cmul(c2, D2[2])));
        float2 P = cmul(cmul(hp1, hm1), cmul(hp2, hm2));
        float inv = 1.0f / (P.x * P.x + P.y * P.y);
        float2 G = make_float2(P.x * inv, -P.y * inv);
        if (kx == 384)      G.y = 0.0f;    // irfft drops imag at Nyquist column
        else if (kx > 384)  G.y = -G.y;    // Hermitian mirror half
        G.x *= scale; G.y *= scale;
        u[s] = cmul(u[s], G);
    }

    // inverse FFT: u[r] is exactly X[jj + 96r] = stage-1 input -> fuse in registers
    dft8<true>(u);
    __syncthreads();                            // all forward stage-3 reads of SB done
#pragma unroll
    for (int s = 0; s < 8; s++) SB[map(8*jj + s)] = u[s];
    __syncthreads();
    stage2_r12<true>(SB, SE, jj, jj < 64, map);
    float2 z[8];
    stage3_r8<true>(SB, SE, jj, map, z);
#pragma unroll
    for (int s = 0; s < 8; s++) {
        int y = jj + 96*s;
        sth(base + (size_t)y * NP + kx, z[s]);
    }
}

// ---------------- Pass 3: inverse row FFT + unpack pairs ----------------
__global__ __launch_bounds__(384) void k_row_inv(float* __restrict__ out)
{
    __shared__ float2 SB[BUF];
    __shared__ float2 SE[EBUF];
    int t = threadIdx.x;
    for (int i = t; i < NP; i += 384) SE[P_(i)] = g_E[i];
    int sub = t / 96, jj = t - sub * 96;
    int p = blockIdx.x / 192;
    int y = ((blockIdx.x - p * 192) << 2) + sub;
    const __half2* in = g_buf + ((size_t)p * NP + y) * NP;
    float2 v[8];
#pragma unroll
    for (int rr = 0; rr < 8; rr++) v[rr] = ldh(in + jj + 96*rr);
    MapRow map; map.base = sub * LLEN;
    stage1_store<true>(v, SB, jj, map);
    __syncthreads();
    stage2_r12<true>(SB, SE, jj, jj < 64, map);
    float2 u[8];
    stage3_r8<true>(SB, SE, jj, map, u);
    float* o1 = out + ((size_t)(2*p)     * NP + y) * NP;
    float* o2 = out + ((size_t)(2*p + 1) * NP + y) * NP;
#pragma unroll
    for (int s = 0; s < 8; s++) {
        int xi = jj + 96*s;
        o1[xi] = u[s].x;
        o2[xi] = u[s].y;
    }
}

extern "C" void kernel_launch(void* const* d_in, const int* in_sizes, int n_in,
                              void* d_out, int out_size)
{
    const float* x = (const float*)d_in[0];
    const float* w = (const float*)d_in[1];
    if (n_in >= 2 && in_sizes[0] == 9) {  // safety: metadata order w,x
        const float* tmp = x; x = w; w = tmp;
    }
    float* out = (float*)d_out;

    k_init_E<<<1, NP>>>();
    k_row_fwd<<<NPAIR * NZROWS / 4, 384>>>(x);
    k_col    <<<NPAIR * 192, 384>>>(w);
    k_row_inv<<<NPAIR * NP / 4, 384>>>(out);
}

// round 12
// speedup vs baseline: 1.7238x; 1.0406x over previous
#include <cuda_runtime.h>
#include <cuda_fp16.h>
#include <math.h>

#define NPAIR 32      // 64 real batches packed as 32 complex images
#define HIN   512
#define WIN   512
#define NP    768     // padded size (both dims)
#define PAD   128
#define NZROWS 512    // nonzero padded rows: y in [PAD, PAD+512)

// padded smem element index: +1 float2 per 16 to break power-of-2 stride conflicts
#define P_(i) ((i) + ((i) >> 4))

#define BUF   3264    // block-wide float2 data buffer: >= P_(3071)+1
#define LLEN  816     // per-line stride in row kernels: >= P_(767)+1
#define EBUF  816

__device__ __half2 g_buf[NPAIR * NP * NP];  // 75 MB fp16 complex scratch
__device__ float2  g_E[NP];                 // e^{-2*pi*i*m/768}
__device__ float2  g_G[NP * NP];            // precomputed filter, scale folded in (4.7 MB)

static __device__ __forceinline__ float2 cmul(float2 a, float2 b) {
    return make_float2(a.x*b.x - a.y*b.y, a.x*b.y + a.y*b.x);
}
static __device__ __forceinline__ float2 cadd(float2 a, float2 b) { return make_float2(a.x+b.x, a.y+b.y); }
static __device__ __forceinline__ float2 csub(float2 a, float2 b) { return make_float2(a.x-b.x, a.y-b.y); }
static __device__ __forceinline__ float2 cconj(float2 a) { return make_float2(a.x, -a.y); }
static __device__ __forceinline__ float2 mul_mi(float2 a) { return make_float2(a.y, -a.x); }  // *(-i)
static __device__ __forceinline__ float2 mul_pi(float2 a) { return make_float2(-a.y, a.x); }  // *(+i)

static __device__ __forceinline__ float2 ldh(const __half2* p) { return __half22float2(*p); }
static __device__ __forceinline__ void sth(__half2* p, float2 v) { *p = __floats2half2_rn(v.x, v.y); }

__global__ void k_init_E() {
    int t = threadIdx.x;
    if (t < NP) {
        double a = -2.0 * 3.14159265358979323846 * (double)t / (double)NP;
        g_E[t] = make_float2((float)cos(a), (float)sin(a));
    }
}

// Precompute G[ky][kx] exactly as the reference's gmf (with full-grid extension),
// ifft 1/768^2 scale folded in. Pure function of (kx, ky); reused by all 32 images.
__global__ __launch_bounds__(256) void k_init_G(const float* __restrict__ w)
{
    int idx = blockIdx.x * 256 + threadIdx.x;
    if (idx >= NP * NP) return;
    int ky = idx / NP;
    int kx = idx - ky * NP;

    int jp = (kx <= 384) ? kx : (NP - kx);
    int j2 = (jp == 0) ? 0 : ((jp == 384) ? 1 : (385 - jp));
    float2 D1[3], D2[3];
#pragma unroll
    for (int a = 0; a < 3; a++) {
        float2 s1 = make_float2(0.f, 0.f), s2 = make_float2(0.f, 0.f);
#pragma unroll
        for (int b = 0; b < 3; b++) {
            float wv = w[a * 3 + b];
            float2 e1 = g_E[(jp * b) % NP];
            float2 e2 = g_E[(j2 * b) % NP];
            s1.x += wv * e1.x; s1.y += wv * e1.y;
            s2.x += wv * e2.x; s2.y += wv * e2.y;
        }
        D1[a] = s1; D2[a] = s2;
    }
    float2 e1 = g_E[ky];
    int k2i = 2 * ky; if (k2i >= NP) k2i -= NP;
    float2 e2 = g_E[k2i];
    float2 c1 = cconj(e1), c2 = cconj(e2);
    float2 hp1 = cadd(D1[0], cadd(cmul(e1, D1[1]), cmul(e2, D1[2])));
    float2 hm1 = cadd(D1[0], cadd(cmul(c1, D1[1]), cmul(c2, D1[2])));
    float2 hp2 = cadd(D2[0], cadd(cmul(e1, D2[1]), cmul(e2, D2[2])));
    float2 hm2 = cadd(D2[0], cadd(cmul(c1, D2[1]), cmul(c2, D2[2])));
    float2 P = cmul(cmul(hp1, hm1), cmul(hp2, hm2));
    float inv = 1.0f / (P.x * P.x + P.y * P.y);
    float2 G = make_float2(P.x * inv, -P.y * inv);
    if (kx == 384)      G.y = 0.0f;    // irfft drops imag at Nyquist column
    else if (kx > 384)  G.y = -G.y;    // Hermitian mirror half
    const float scale = 1.0f / ((float)NP * (float)NP);
    G.x *= scale; G.y *= scale;
    g_G[idx] = G;
}

// ---------------- register DFT kernels ----------------
template<bool INV>
static __device__ __forceinline__ void dft4(float2 v[4]) {
    float2 t0 = cadd(v[0], v[2]), t1 = csub(v[0], v[2]);
    float2 t2 = cadd(v[1], v[3]), t3 = csub(v[1], v[3]);
    float2 jt3 = INV ? mul_pi(t3) : mul_mi(t3);
    v[0] = cadd(t0, t2); v[2] = csub(t0, t2);
    v[1] = cadd(t1, jt3); v[3] = csub(t1, jt3);
}

template<bool INV>
static __device__ __forceinline__ void dft8(float2 v[8]) {
    float2 e[4] = {v[0], v[2], v[4], v[6]};
    float2 o[4] = {v[1], v[3], v[5], v[7]};
    dft4<INV>(e); dft4<INV>(o);
    const float rh = 0.70710678118654752f;
    o[1] = cmul(o[1], make_float2(rh, INV ? rh : -rh));
    o[2] = INV ? mul_pi(o[2]) : mul_mi(o[2]);
    o[3] = cmul(o[3], make_float2(-rh, INV ? rh : -rh));
#pragma unroll
    for (int k = 0; k < 4; k++) { v[k] = cadd(e[k], o[k]); v[k+4] = csub(e[k], o[k]); }
}

// 12-point DFT, natural-order in and out.  12 = 4 x 3 Cooley-Tukey.
template<bool INV>
static __device__ __forceinline__ void dft12(float2 v[12]) {
    const float H = 0.5f, S = 0.8660254037844386f;
    float2 c0[4], c1[4], c2[4];
    {
        float2 b[4];
        b[0]=v[0]; b[1]=v[3]; b[2]=v[6]; b[3]=v[9];  dft4<INV>(b);
        c0[0]=b[0]; c0[1]=b[1]; c0[2]=b[2]; c0[3]=b[3];
        b[0]=v[1]; b[1]=v[4]; b[2]=v[7]; b[3]=v[10]; dft4<INV>(b);
        c1[0]=b[0]; c1[1]=b[1]; c1[2]=b[2]; c1[3]=b[3];
        b[0]=v[2]; b[1]=v[5]; b[2]=v[8]; b[3]=v[11]; dft4<INV>(b);
        c2[0]=b[0]; c2[1]=b[1]; c2[2]=b[2]; c2[3]=b[3];
    }
    const float sgn = INV ? 1.f : -1.f;
    c1[1] = cmul(c1[1], make_float2(S, sgn*H));
    c1[2] = cmul(c1[2], make_float2(H, sgn*S));
    c1[3] = INV ? mul_pi(c1[3]) : mul_mi(c1[3]);
    c2[1] = cmul(c2[1], make_float2(H,  sgn*S));
    c2[2] = cmul(c2[2], make_float2(-H, sgn*S));
    c2[3] = make_float2(-c2[3].x, -c2[3].y);
    const float d = INV ? S : -S;
#pragma unroll
    for (int k1 = 0; k1 < 4; k1++) {
        float2 t = cadd(c1[k1], c2[k1]);
        float2 u = csub(c1[k1], c2[k1]);
        float2 x0 = cadd(c0[k1], t);
        float2 m = make_float2(c0[k1].x - 0.5f*t.x, c0[k1].y - 0.5f*t.y);
        float2 idu = make_float2(-d*u.y, d*u.x);
        v[k1]     = x0;
        v[4 + k1] = cadd(m, idu);
        v[8 + k1] = csub(m, idu);
    }
}

// log-depth twiddle powers: tw[r] = w1^r, depth <= ceil(log2 r); pure registers.
template<int N>
static __device__ __forceinline__ void twpow(float2 w1, float2 tw[N]) {
    tw[1] = w1;
#pragma unroll
    for (int r = 2; r < N; r++) tw[r] = cmul(tw[r >> 1], tw[r - (r >> 1)]);
}

// ---------------- Stockham stages: 768 = 8(NS=1) * 12(NS=8) * 8(NS=96) ----------------
struct MapRow {
    int base;
    __device__ __forceinline__ int operator()(int e) const { return base + P_(e); }
};
struct MapCol {
    int tx;
    __device__ __forceinline__ int operator()(int e) const { int b = (e << 2) + tx; return P_(b); }
};

template<bool INV, class M>
static __device__ __forceinline__ void stage1_store(float2 v[8], float2* buf, int j, M map) {
    dft8<INV>(v);
#pragma unroll
    for (int s = 0; s < 8; s++) buf[map(8*j + s)] = v[s];
}

// active = (j < 64). ALL threads must call (contains block barrier).
template<bool INV, class M>
static __device__ __forceinline__ void stage2_r12(float2* buf, const float2* E, int j, bool active, M map) {
    float2 v[12];
    int m = j & 7;
    if (active) {
#pragma unroll
        for (int r = 0; r < 12; r++) v[r] = buf[map(j + 64*r)];
        float2 w1 = E[P_(8*m)];
        if (INV) w1.y = -w1.y;
        float2 tw[12];
        twpow<12>(w1, tw);
#pragma unroll
        for (int r = 1; r < 12; r++) v[r] = cmul(v[r], tw[r]);
        dft12<INV>(v);
    }
    __syncthreads();
    if (active) {
        int base = 12*j - 11*m;
#pragma unroll
        for (int s = 0; s < 12; s++) buf[map(base + 8*s)] = v[s];
    }
    __syncthreads();
}

// output in v: v[s] = X[j + 96 s]
template<bool INV, class M>
static __device__ __forceinline__ void stage3_r8(const float2* buf, const float2* E, int j, M map, float2 v[8]) {
#pragma unroll
    for (int r = 0; r < 8; r++) v[r] = buf[map(j + 96*r)];
    float2 w1 = E[P_(j)];
    if (INV) w1.y = -w1.y;
    float2 tw[8];
    twpow<8>(w1, tw);
#pragma unroll
    for (int r = 1; r < 8; r++) v[r] = cmul(v[r], tw[r]);
    dft8<INV>(v);
}

// ---------------- Pass 1: pad + pack pairs + forward row FFT (512 rows/image) ----------------
__global__ __launch_bounds__(384) void k_row_fwd(const float* __restrict__ x)
{
    __shared__ float2 SB[BUF];
    __shared__ float2 SE[EBUF];
    int t = threadIdx.x;
    for (int i = t; i < NP; i += 384) SE[P_(i)] = g_E[i];
    int sub = t / 96, jj = t - sub * 96;
    int p = blockIdx.x >> 7;                    // /128
    int r = ((blockIdx.x & 127) << 2) + sub;    // row in [0,512)
    int y = PAD + r;
    const float* r1 = x + ((size_t)(2*p)     * HIN + r) * WIN;
    const float* r2 = x + ((size_t)(2*p + 1) * HIN + r) * WIN;
    float2 v[8];
#pragma unroll
    for (int rr = 0; rr < 8; rr++) {
        int xi = jj + 96*rr;
        float2 val = make_float2(0.f, 0.f);
        if (xi >= PAD && xi < PAD + WIN) {
            val.x = r1[xi - PAD];
            val.y = r2[xi - PAD];
        }
        v[rr] = val;
    }
    MapRow map; map.base = sub * LLEN;
    stage1_store<false>(v, SB, jj, map);
    __syncthreads();                            // SE + stage1 visible
    stage2_r12<false>(SB, SE, jj, jj < 64, map);
    float2 u[8];
    stage3_r8<false>(SB, SE, jj, map, u);
    __half2* o = g_buf + ((size_t)p * NP + y) * NP;
#pragma unroll
    for (int s = 0; s < 8; s++) sth(o + jj + 96*s, u[s]);
}

// ---------------- Pass 2: column FFT * G * column IFFT (in place) ----------------
__global__ __launch_bounds__(384) void k_col()
{
    __shared__ float2 SB[BUF];
    __shared__ float2 SE[EBUF];
    int t = threadIdx.x;
    for (int i = t; i < NP; i += 384) SE[P_(i)] = g_E[i];
    int tx = t & 3;
    int jj = t >> 2;                            // [0,96)
    int p = blockIdx.x / 192;
    int g = blockIdx.x - p * 192;
    int kx = (g << 2) + tx;
    __half2* base = g_buf + (size_t)p * NP * NP;
    MapCol map; map.tx = tx;

    float2 v[8];
#pragma unroll
    for (int rr = 0; rr < 8; rr++) {
        int y = jj + 96*rr;
        float2 val = make_float2(0.f, 0.f);
        if (y >= PAD && y < PAD + NZROWS)
            val = ldh(base + (size_t)y * NP + kx);
        v[rr] = val;
    }
    stage1_store<false>(v, SB, jj, map);
    __syncthreads();
    stage2_r12<false>(SB, SE, jj, jj < 64, map);
    float2 u[8];
    stage3_r8<false>(SB, SE, jj, map, u);       // u[s] = spectrum at ky = jj+96s

    // apply precomputed filter (L2-resident; reused by all 32 images)
    const float2* Gp = g_G + kx;
#pragma unroll
    for (int s = 0; s < 8; s++) {
        int ky = jj + 96*s;
        float2 G = Gp[(size_t)ky * NP];
        u[s] = cmul(u[s], G);
    }

    // inverse FFT: u[r] is exactly X[jj + 96r] = stage-1 input -> fuse in registers
    dft8<true>(u);
    __syncthreads();                            // all forward stage-3 reads of SB done
#pragma unroll
    for (int s = 0; s < 8; s++) SB[map(8*jj + s)] = u[s];
    __syncthreads();
    stage2_r12<true>(SB, SE, jj, jj < 64, map);
    float2 z[8];
    stage3_r8<true>(SB, SE, jj, map, z);
#pragma unroll
    for (int s = 0; s < 8; s++) {
        int y = jj + 96*s;
        sth(base + (size_t)y * NP + kx, z[s]);
    }
}

// ---------------- Pass 3: inverse row FFT + unpack pairs ----------------
__global__ __launch_bounds__(384) void k_row_inv(float* __restrict__ out)
{
    __shared__ float2 SB[BUF];
    __shared__ float2 SE[EBUF];
    int t = threadIdx.x;
    for (int i = t; i < NP; i += 384) SE[P_(i)] = g_E[i];
    int sub = t / 96, jj = t - sub * 96;
    int p = blockIdx.x / 192;
    int y = ((blockIdx.x - p * 192) << 2) + sub;
    const __half2* in = g_buf + ((size_t)p * NP + y) * NP;
    float2 v[8];
#pragma unroll
    for (int rr = 0; rr < 8; rr++) v[rr] = ldh(in + jj + 96*rr);
    MapRow map; map.base = sub * LLEN;
    stage1_store<true>(v, SB, jj, map);
    __syncthreads();
    stage2_r12<true>(SB, SE, jj, jj < 64, map);
    float2 u[8];
    stage3_r8<true>(SB, SE, jj, map, u);
    float* o1 = out + ((size_t)(2*p)     * NP + y) * NP;
    float* o2 = out + ((size_t)(2*p + 1) * NP + y) * NP;
#pragma unroll
    for (int s = 0; s < 8; s++) {
        int xi = jj + 96*s;
        o1[xi] = u[s].x;
        o2[xi] = u[s].y;
    }
}

extern "C" void kernel_launch(void* const* d_in, const int* in_sizes, int n_in,
                              void* d_out, int out_size)
{
    const float* x = (const float*)d_in[0];
    const float* w = (const float*)d_in[1];
    if (n_in >= 2 && in_sizes[0] == 9) {  // safety: metadata order w,x
        const float* tmp = x; x = w; w = tmp;
    }
    float* out = (float*)d_out;

    k_init_E<<<1, NP>>>();
    k_init_G<<<(NP * NP + 255) / 256, 256>>>(w);
    k_row_fwd<<<NPAIR * NZROWS / 4, 384>>>(x);
    k_col    <<<NPAIR * 192, 384>>>();
    k_row_inv<<<NPAIR * NP / 4, 384>>>(out);
}

// round 14
// speedup vs baseline: 1.8572x; 1.0774x over previous
#include <cuda_runtime.h>
#include <cuda_fp16.h>
#include <math.h>

#define NPAIR 32      // 64 real batches packed as 32 complex images
#define HIN   512
#define WIN   512
#define NP    768     // padded size (both dims)
#define PAD   128
#define NZROWS 512    // nonzero padded rows: y in [PAD, PAD+512)

// padded smem element index: +1 float2 per 16 to break power-of-2 stride conflicts
#define P_(i) ((i) + ((i) >> 4))

#define BUF   3264    // block-wide float2 data buffer: >= P_(3071)+1
#define LLEN  816     // per-line stride in row kernels: >= P_(767)+1
#define EBUF  816

__device__ __half2 g_buf[NPAIR * NP * NP];  // 75 MB fp16 complex scratch
__device__ float2  g_E[NP];                 // e^{-2*pi*i*m/768}
__device__ float2  g_G[NP * NP];            // precomputed filter, scale folded in (4.7 MB)

static __device__ __forceinline__ float2 cmul(float2 a, float2 b) {
    return make_float2(a.x*b.x - a.y*b.y, a.x*b.y + a.y*b.x);
}
static __device__ __forceinline__ float2 cadd(float2 a, float2 b) { return make_float2(a.x+b.x, a.y+b.y); }
static __device__ __forceinline__ float2 csub(float2 a, float2 b) { return make_float2(a.x-b.x, a.y-b.y); }
static __device__ __forceinline__ float2 cconj(float2 a) { return make_float2(a.x, -a.y); }
static __device__ __forceinline__ float2 mul_mi(float2 a) { return make_float2(a.y, -a.x); }  // *(-i)
static __device__ __forceinline__ float2 mul_pi(float2 a) { return make_float2(-a.y, a.x); }  // *(+i)

static __device__ __forceinline__ float2 ldh(const __half2* p) { return __half22float2(*p); }
static __device__ __forceinline__ void sth(__half2* p, float2 v) { *p = __floats2half2_rn(v.x, v.y); }

__global__ void k_init_E() {
    int t = threadIdx.x;
    if (t < NP) {
        double a = -2.0 * 3.14159265358979323846 * (double)t / (double)NP;
        g_E[t] = make_float2((float)cos(a), (float)sin(a));
    }
}

// Precompute G[ky][kx] exactly as the reference's gmf (with full-grid extension),
// ifft 1/768^2 scale folded in. Pure function of (kx, ky); reused by all 32 images.
__global__ __launch_bounds__(256) void k_init_G(const float* __restrict__ w)
{
    int idx = blockIdx.x * 256 + threadIdx.x;
    if (idx >= NP * NP) return;
    int ky = idx / NP;
    int kx = idx - ky * NP;

    int jp = (kx <= 384) ? kx : (NP - kx);
    int j2 = (jp == 0) ? 0 : ((jp == 384) ? 1 : (385 - jp));
    float2 D1[3], D2[3];
#pragma unroll
    for (int a = 0; a < 3; a++) {
        float2 s1 = make_float2(0.f, 0.f), s2 = make_float2(0.f, 0.f);
#pragma unroll
        for (int b = 0; b < 3; b++) {
            float wv = w[a * 3 + b];
            float2 e1 = g_E[(jp * b) % NP];
            float2 e2 = g_E[(j2 * b) % NP];
            s1.x += wv * e1.x; s1.y += wv * e1.y;
            s2.x += wv * e2.x; s2.y += wv * e2.y;
        }
        D1[a] = s1; D2[a] = s2;
    }
    float2 e1 = g_E[ky];
    int k2i = 2 * ky; if (k2i >= NP) k2i -= NP;
    float2 e2 = g_E[k2i];
    float2 c1 = cconj(e1), c2 = cconj(e2);
    float2 hp1 = cadd(D1[0], cadd(cmul(e1, D1[1]), cmul(e2, D1[2])));
    float2 hm1 = cadd(D1[0], cadd(cmul(c1, D1[1]), cmul(c2, D1[2])));
    float2 hp2 = cadd(D2[0], cadd(cmul(e1, D2[1]), cmul(e2, D2[2])));
    float2 hm2 = cadd(D2[0], cadd(cmul(c1, D2[1]), cmul(c2, D2[2])));
    float2 P = cmul(cmul(hp1, hm1), cmul(hp2, hm2));
    float inv = 1.0f / (P.x * P.x + P.y * P.y);
    float2 G = make_float2(P.x * inv, -P.y * inv);
    if (kx == 384)      G.y = 0.0f;    // irfft drops imag at Nyquist column
    else if (kx > 384)  G.y = -G.y;    // Hermitian mirror half
    const float scale = 1.0f / ((float)NP * (float)NP);
    G.x *= scale; G.y *= scale;
    g_G[idx] = G;
}

// ---------------- register DFT kernels ----------------
template<bool INV>
static __device__ __forceinline__ void dft4(float2 v[4]) {
    float2 t0 = cadd(v[0], v[2]), t1 = csub(v[0], v[2]);
    float2 t2 = cadd(v[1], v[3]), t3 = csub(v[1], v[3]);
    float2 jt3 = INV ? mul_pi(t3) : mul_mi(t3);
    v[0] = cadd(t0, t2); v[2] = csub(t0, t2);
    v[1] = cadd(t1, jt3); v[3] = csub(t1, jt3);
}

template<bool INV>
static __device__ __forceinline__ void dft8(float2 v[8]) {
    float2 e[4] = {v[0], v[2], v[4], v[6]};
    float2 o[4] = {v[1], v[3], v[5], v[7]};
    dft4<INV>(e); dft4<INV>(o);
    const float rh = 0.70710678118654752f;
    o[1] = cmul(o[1], make_float2(rh, INV ? rh : -rh));
    o[2] = INV ? mul_pi(o[2]) : mul_mi(o[2]);
    o[3] = cmul(o[3], make_float2(-rh, INV ? rh : -rh));
#pragma unroll
    for (int k = 0; k < 4; k++) { v[k] = cadd(e[k], o[k]); v[k+4] = csub(e[k], o[k]); }
}

// 12-point DFT, natural-order in and out.  12 = 4 x 3 Cooley-Tukey.
template<bool INV>
static __device__ __forceinline__ void dft12(float2 v[12]) {
    const float H = 0.5f, S = 0.8660254037844386f;
    float2 c0[4], c1[4], c2[4];
    {
        float2 b[4];
        b[0]=v[0]; b[1]=v[3]; b[2]=v[6]; b[3]=v[9];  dft4<INV>(b);
        c0[0]=b[0]; c0[1]=b[1]; c0[2]=b[2]; c0[3]=b[3];
        b[0]=v[1]; b[1]=v[4]; b[2]=v[7]; b[3]=v[10]; dft4<INV>(b);
        c1[0]=b[0]; c1[1]=b[1]; c1[2]=b[2]; c1[3]=b[3];
        b[0]=v[2]; b[1]=v[5]; b[2]=v[8]; b[3]=v[11]; dft4<INV>(b);
        c2[0]=b[0]; c2[1]=b[1]; c2[2]=b[2]; c2[3]=b[3];
    }
    const float sgn = INV ? 1.f : -1.f;
    c1[1] = cmul(c1[1], make_float2(S, sgn*H));
    c1[2] = cmul(c1[2], make_float2(H, sgn*S));
    c1[3] = INV ? mul_pi(c1[3]) : mul_mi(c1[3]);
    c2[1] = cmul(c2[1], make_float2(H,  sgn*S));
    c2[2] = cmul(c2[2], make_float2(-H, sgn*S));
    c2[3] = make_float2(-c2[3].x, -c2[3].y);
    const float d = INV ? S : -S;
#pragma unroll
    for (int k1 = 0; k1 < 4; k1++) {
        float2 t = cadd(c1[k1], c2[k1]);
        float2 u = csub(c1[k1], c2[k1]);
        float2 x0 = cadd(c0[k1], t);
        float2 m = make_float2(c0[k1].x - 0.5f*t.x, c0[k1].y - 0.5f*t.y);
        float2 idu = make_float2(-d*u.y, d*u.x);
        v[k1]     = x0;
        v[4 + k1] = cadd(m, idu);
        v[8 + k1] = csub(m, idu);
    }
}

// log-depth twiddle powers: tw[r] = w1^r, depth <= ceil(log2 r); pure registers.
template<int N>
static __device__ __forceinline__ void twpow(float2 w1, float2 tw[N]) {
    tw[1] = w1;
#pragma unroll
    for (int r = 2; r < N; r++) tw[r] = cmul(tw[r >> 1], tw[r - (r >> 1)]);
}

// ---------------- Stockham stages: 768 = 8(NS=1) * 12(NS=8) * 8(NS=96) ----------------
struct MapRow {
    int base;
    __device__ __forceinline__ int operator()(int e) const { return base + P_(e); }
};
struct MapCol {
    int tx;
    __device__ __forceinline__ int operator()(int e) const { int b = (e << 2) + tx; return P_(b); }
};

template<bool INV, class M>
static __device__ __forceinline__ void stage1_store(float2 v[8], float2* buf, int j, M map) {
    dft8<INV>(v);
#pragma unroll
    for (int s = 0; s < 8; s++) buf[map(8*j + s)] = v[s];
}

// active = (j < 64). ALL threads must call (contains block barrier).
template<bool INV, class M>
static __device__ __forceinline__ void stage2_r12(float2* buf, const float2* E, int j, bool active, M map) {
    float2 v[12];
    int m = j & 7;
    if (active) {
#pragma unroll
        for (int r = 0; r < 12; r++) v[r] = buf[map(j + 64*r)];
        float2 w1 = E[P_(8*m)];
        if (INV) w1.y = -w1.y;
        float2 tw[12];
        twpow<12>(w1, tw);
#pragma unroll
        for (int r = 1; r < 12; r++) v[r] = cmul(v[r], tw[r]);
        dft12<INV>(v);
    }
    __syncthreads();
    if (active) {
        int base = 12*j - 11*m;
#pragma unroll
        for (int s = 0; s < 12; s++) buf[map(base + 8*s)] = v[s];
    }
    __syncthreads();
}

// output in v: v[s] = X[j + 96 s]
template<bool INV, class M>
static __device__ __forceinline__ void stage3_r8(const float2* buf, const float2* E, int j, M map, float2 v[8]) {
#pragma unroll
    for (int r = 0; r < 8; r++) v[r] = buf[map(j + 96*r)];
    float2 w1 = E[P_(j)];
    if (INV) w1.y = -w1.y;
    float2 tw[8];
    twpow<8>(w1, tw);
#pragma unroll
    for (int r = 1; r < 8; r++) v[r] = cmul(v[r], tw[r]);
    dft8<INV>(v);
}

// ---------------- Pass 1: pad + pack pairs + forward row FFT (512 rows/image) ----------------
__global__ __launch_bounds__(384) void k_row_fwd(const float* __restrict__ x)
{
    __shared__ float2 SB[BUF];
    __shared__ float2 SE[EBUF];
    int t = threadIdx.x;
    for (int i = t; i < NP; i += 384) SE[P_(i)] = g_E[i];
    int sub = t / 96, jj = t - sub * 96;
    int p = blockIdx.x >> 7;                    // /128
    int r = ((blockIdx.x & 127) << 2) + sub;    // row in [0,512)
    int y = PAD + r;
    const float* r1 = x + ((size_t)(2*p)     * HIN + r) * WIN;
    const float* r2 = x + ((size_t)(2*p + 1) * HIN + r) * WIN;
    float2 v[8];
#pragma unroll
    for (int rr = 0; rr < 8; rr++) {
        int xi = jj + 96*rr;
        float2 val = make_float2(0.f, 0.f);
        if (xi >= PAD && xi < PAD + WIN) {
            val.x = r1[xi - PAD];
            val.y = r2[xi - PAD];
        }
        v[rr] = val;
    }
    MapRow map; map.base = sub * LLEN;
    stage1_store<false>(v, SB, jj, map);
    __syncthreads();                            // SE + stage1 visible
    stage2_r12<false>(SB, SE, jj, jj < 64, map);
    float2 u[8];
    stage3_r8<false>(SB, SE, jj, map, u);
    __half2* o = g_buf + ((size_t)p * NP + y) * NP;
#pragma unroll
    for (int s = 0; s < 8; s++) sth(o + jj + 96*s, u[s]);
}

// ---------------- Pass 2: column FFT * G * column IFFT (in place) ----------------
__global__ __launch_bounds__(384, 4) void k_col()
{
    __shared__ float2 SB[BUF];
    __shared__ float2 SE[EBUF];
    int t = threadIdx.x;
    for (int i = t; i < NP; i += 384) SE[P_(i)] = g_E[i];
    int tx = t & 3;
    int jj = t >> 2;                            // [0,96)
    int p = blockIdx.x / 192;
    int g = blockIdx.x - p * 192;
    int kx = (g << 2) + tx;
    __half2* base = g_buf + (size_t)p * NP * NP;
    MapCol map; map.tx = tx;

    float2 v[8];
#pragma unroll
    for (int rr = 0; rr < 8; rr++) {
        int y = jj + 96*rr;
        float2 val = make_float2(0.f, 0.f);
        if (y >= PAD && y < PAD + NZROWS)
            val = ldh(base + (size_t)y * NP + kx);
        v[rr] = val;
    }
    stage1_store<false>(v, SB, jj, map);
    __syncthreads();
    stage2_r12<false>(SB, SE, jj, jj < 64, map);
    float2 u[8];
    stage3_r8<false>(SB, SE, jj, map, u);       // u[s] = spectrum at ky = jj+96s

    // apply precomputed filter (L2-resident; reused by all 32 images)
    const float2* Gp = g_G + kx;
#pragma unroll
    for (int s = 0; s < 8; s++) {
        int ky = jj + 96*s;
        float2 G = Gp[(size_t)ky * NP];
        u[s] = cmul(u[s], G);
    }

    // inverse FFT: u[r] is exactly X[jj + 96r] = stage-1 input -> fuse in registers
    dft8<true>(u);
    __syncthreads();                            // all forward stage-3 reads of SB done
#pragma unroll
    for (int s = 0; s < 8; s++) SB[map(8*jj + s)] = u[s];
    __syncthreads();
    stage2_r12<true>(SB, SE, jj, jj < 64, map);
    float2 z[8];
    stage3_r8<true>(SB, SE, jj, map, z);
#pragma unroll
    for (int s = 0; s < 8; s++) {
        int y = jj + 96*s;
        sth(base + (size_t)y * NP + kx, z[s]);
    }
}

// ---------------- Pass 3: inverse row FFT + unpack pairs ----------------
__global__ __launch_bounds__(384) void k_row_inv(float* __restrict__ out)
{
    __shared__ float2 SB[BUF];
    __shared__ float2 SE[EBUF];
    int t = threadIdx.x;
    for (int i = t; i < NP; i += 384) SE[P_(i)] = g_E[i];
    int sub = t / 96, jj = t - sub * 96;
    int p = blockIdx.x / 192;
    int y = ((blockIdx.x - p * 192) << 2) + sub;
    const __half2* in = g_buf + ((size_t)p * NP + y) * NP;
    float2 v[8];
#pragma unroll
    for (int rr = 0; rr < 8; rr++) v[rr] = ldh(in + jj + 96*rr);
    MapRow map; map.base = sub * LLEN;
    stage1_store<true>(v, SB, jj, map);
    __syncthreads();
    stage2_r12<true>(SB, SE, jj, jj < 64, map);
    float2 u[8];
    stage3_r8<true>(SB, SE, jj, map, u);
    float* o1 = out + ((size_t)(2*p)     * NP + y) * NP;
    float* o2 = out + ((size_t)(2*p + 1) * NP + y) * NP;
#pragma unroll
    for (int s = 0; s < 8; s++) {
        int xi = jj + 96*s;
        o1[xi] = u[s].x;
        o2[xi] = u[s].y;
    }
}

extern "C" void kernel_launch(void* const* d_in, const int* in_sizes, int n_in,
                              void* d_out, int out_size)
{
    const float* x = (const float*)d_in[0];
    const float* w = (const float*)d_in[1];
    if (n_in >= 2 && in_sizes[0] == 9) {  // safety: metadata order w,x
        const float* tmp = x; x = w; w = tmp;
    }
    float* out = (float*)d_out;

    k_init_E<<<1, NP>>>();
    k_init_G<<<(NP * NP + 255) / 256, 256>>>(w);
    k_row_fwd<<<NPAIR * NZROWS / 4, 384>>>(x);
    k_col    <<<NPAIR * 192, 384>>>();
    k_row_inv<<<NPAIR * NP / 4, 384>>>(out);
}